// round 2
// baseline (speedup 1.0000x reference)
#include <cuda_runtime.h>
#include <math.h>

#define SQ   400
#define BB   128
#define HH   512
#define EE   300
#define G3   1536
#define NCOL 3072

typedef unsigned long long u64;

__device__ float g_gi[(size_t)SQ * NCOL * BB];      // [t][col(3072)][b(128)]
__device__ float g_y0[(size_t)SQ * 1024 * BB];      // [t][k(1024)][b(128)]
__device__ float g_hdup[2][2][HH][2 * BB];          // [buf][dir][k][2*b] duplicated pairs
__device__ unsigned g_bar;

__device__ __forceinline__ void fma2(u64 &d, u64 a, u64 b) {
    asm("fma.rn.f32x2 %0, %1, %2, %0;" : "+l"(d) : "l"(a), "l"(b));
}
__device__ __forceinline__ u64 pack2(float x, float y) {
    u64 r; asm("mov.b64 %0, {%1, %2};" : "=l"(r) : "f"(x), "f"(y)); return r;
}
__device__ __forceinline__ float2 unpack2(u64 v) {
    float2 f;
    f.x = __uint_as_float((unsigned)(v & 0xffffffffull));
    f.y = __uint_as_float((unsigned)(v >> 32));
    return f;
}

__global__ void init_kernel() {
    float* p = &g_hdup[0][0][0][0];
    size_t n = 2ull * 2 * HH * 2 * BB;
    for (size_t i = blockIdx.x * blockDim.x + threadIdx.x; i < n; i += (size_t)gridDim.x * blockDim.x)
        p[i] = 0.0f;
    if (blockIdx.x == 0 && threadIdx.x == 0) g_bar = 0u;
}

// C[t][col][b] = bias[col] + sum_k A[b][k] * W[col][k]
// GATHER: A row b = emb[X[t*128+b]] (K=300). Else A[k][b] = g_y0[t][k][b] (K=1024).
template <bool GATHER>
__global__ __launch_bounds__(256, 2) void gemm_kernel(
    const float* __restrict__ Aemb, const int* __restrict__ X,
    const float* __restrict__ W, const float* __restrict__ bias, int K)
{
    __shared__ __align__(16) float As[2][8][256];   // [kk][2*m] dup pairs
    __shared__ __align__(16) float Bs[2][8][128];

    const int t     = blockIdx.y;
    const int nbase = blockIdx.x * 128;
    const int tid   = threadIdx.x;
    const int tx    = tid & 15;
    const int ty    = tid >> 4;
    const int lm    = tid >> 1;
    const int lk    = (tid & 1) * 4;
    const int kk8   = tid >> 5;          // !GATHER: kk index 0..7
    const int b0    = (tid & 31) * 4;    // !GATHER: 4 consecutive b

    const float* arow;
    if (GATHER) arow = Aemb + (size_t)X[t * 128 + lm] * K;
    else        arow = g_y0 + (size_t)t * 1024 * 128;
    const float* brow = W + (size_t)(nbase + lm) * K;

    u64 acc[8][4];
#pragma unroll
    for (int r = 0; r < 8; r++)
#pragma unroll
        for (int c = 0; c < 4; c++) acc[r][c] = 0ull;

    const int nk = (K + 7) >> 3;

    float4 a4, b4;
    if (GATHER) a4 = (lk < K) ? *(const float4*)(arow + lk) : make_float4(0,0,0,0);
    else        a4 = *(const float4*)(arow + (size_t)kk8 * 128 + b0);
    b4 = (lk < K) ? *(const float4*)(brow + lk) : make_float4(0,0,0,0);

    for (int it = 0; it < nk; it++) {
        const int buf = it & 1;
#pragma unroll
        for (int i = 0; i < 4; i++) {
            float va = (&a4.x)[i];
            if (GATHER) *(u64*)&As[buf][lk + i][2 * lm] = pack2(va, va);
            else        *(u64*)&As[buf][kk8][2 * (b0 + i)] = pack2(va, va);
            Bs[buf][lk + i][lm] = (&b4.x)[i];
        }
        __syncthreads();
        if (it + 1 < nk) {
            int kn = (it + 1) * 8 + lk;
            if (GATHER) a4 = (kn < K) ? *(const float4*)(arow + kn) : make_float4(0,0,0,0);
            else        a4 = *(const float4*)(arow + ((size_t)(it + 1) * 8 + kk8) * 128 + b0);
            b4 = (kn < K) ? *(const float4*)(brow + kn) : make_float4(0,0,0,0);
        }
#pragma unroll
        for (int kk = 0; kk < 8; kk++) {
            u64 ad[8];
#pragma unroll
            for (int r2 = 0; r2 < 4; r2++) {
                ulonglong2 aa = *(const ulonglong2*)&As[buf][kk][ty * 16 + r2 * 4];
                ad[2 * r2] = aa.x; ad[2 * r2 + 1] = aa.y;
            }
            u64 bp[4];
#pragma unroll
            for (int c2 = 0; c2 < 2; c2++) {
                ulonglong2 bv = *(const ulonglong2*)&Bs[buf][kk][tx * 8 + c2 * 4];
                bp[2 * c2] = bv.x; bp[2 * c2 + 1] = bv.y;
            }
#pragma unroll
            for (int r = 0; r < 8; r++)
#pragma unroll
                for (int c = 0; c < 4; c++) fma2(acc[r][c], ad[r], bp[c]);
        }
        __syncthreads();
    }

    float* cbase = g_gi + ((size_t)t * NCOL + nbase + tx * 8) * 128 + ty * 8;
#pragma unroll
    for (int c = 0; c < 8; c++) {
        float bv = bias[nbase + tx * 8 + c];
        float v[8];
#pragma unroll
        for (int r = 0; r < 8; r++) {
            float2 f = unpack2(acc[r][c >> 1]);
            v[r] = ((c & 1) ? f.y : f.x) + bv;
        }
        float4* dst = (float4*)(cbase + (size_t)c * 128);
        dst[0] = make_float4(v[0], v[1], v[2], v[3]);
        dst[1] = make_float4(v[4], v[5], v[6], v[7]);
    }
}

// Persistent recurrence: 128 CTAs (cta>>6 = dir, (cta&63)*8 = jbase), 256 thr.
template <bool WRITE_Y>
__global__ __launch_bounds__(256, 1) void recur_kernel(
    const float* __restrict__ Whh, const float* __restrict__ bhh)
{
    extern __shared__ float w_s[];   // [512][3][8] = 48KB: w_s[k*24+g*8+jj]
    const int cta   = blockIdx.x;
    const int d     = cta >> 6;
    const int jbase = (cta & 63) * 8;
    const int tid   = threadIdx.x;
    const int bb    = tid & 63;
    const int cg    = tid >> 6;
    const int jj0   = 2 * cg;

    for (int idx = tid; idx < 512 * 24; idx += 256) {
        int k = idx / 24, r = idx % 24, g = r >> 3, jj = r & 7;
        w_s[idx] = Whh[((size_t)d * G3 + g * HH + jbase + jj) * HH + k];
    }
    float bh[3][2];
#pragma unroll
    for (int g = 0; g < 3; g++)
#pragma unroll
        for (int jx = 0; jx < 2; jx++)
            bh[g][jx] = bhh[(size_t)d * G3 + g * HH + jbase + jj0 + jx];
    __syncthreads();

    for (int t = 0; t < SQ; t++) {
        const int pr = t & 1, pw = pr ^ 1;
        const u64* hsrc = (const u64*)&g_hdup[pr][d][0][0];

        u64 acc[2][3];
#pragma unroll
        for (int i = 0; i < 2; i++)
#pragma unroll
            for (int g = 0; g < 3; g++) acc[i][g] = 0ull;

        // 8-deep register prefetch ring over k
        u64 hb[8][2];
#pragma unroll
        for (int j = 0; j < 8; j++) {
            hb[j][0] = __ldcg(hsrc + j * 128 + bb);
            hb[j][1] = __ldcg(hsrc + j * 128 + bb + 64);
        }
        for (int k0 = 0; k0 < HH; k0 += 8) {
#pragma unroll
            for (int u = 0; u < 8; u++) {
                const int k = k0 + u;
                const u64* wrow = (const u64*)(w_s + k * 24);
                u64 wr = wrow[cg], wz = wrow[4 + cg], wn = wrow[8 + cg];
                u64 h0 = hb[u][0], h1 = hb[u][1];
                fma2(acc[0][0], h0, wr); fma2(acc[0][1], h0, wz); fma2(acc[0][2], h0, wn);
                fma2(acc[1][0], h1, wr); fma2(acc[1][1], h1, wz); fma2(acc[1][2], h1, wn);
                if (k0 + 8 < HH) {
                    hb[u][0] = __ldcg(hsrc + (k0 + 8 + u) * 128 + bb);
                    hb[u][1] = __ldcg(hsrc + (k0 + 8 + u) * 128 + bb + 64);
                }
            }
        }

        const float* git = g_gi + (size_t)t * NCOL * 128;
#pragma unroll
        for (int bi = 0; bi < 2; bi++) {
            const int b = bb + 64 * bi;
            float2 fr = unpack2(acc[bi][0]);
            float2 fz = unpack2(acc[bi][1]);
            float2 fn = unpack2(acc[bi][2]);
#pragma unroll
            for (int jx = 0; jx < 2; jx++) {
                const int jg = jbase + jj0 + jx;
                float ghr = (jx ? fr.y : fr.x) + bh[0][jx];
                float ghz = (jx ? fz.y : fz.x) + bh[1][jx];
                float ghn = (jx ? fn.y : fn.x) + bh[2][jx];
                float ir  = git[((size_t)(d * G3 + jg)) * 128 + b];
                float iz  = git[((size_t)(d * G3 + HH + jg)) * 128 + b];
                float in_ = git[((size_t)(d * G3 + 2 * HH + jg)) * 128 + b];
                float r = 1.0f / (1.0f + expf(-(ir + ghr)));
                float z = 1.0f / (1.0f + expf(-(iz + ghz)));
                float hold = __ldcg(&g_hdup[pr][d][jg][2 * b]);
                float n = tanhf(in_ + r * ghn);
                float hnew = (1.0f - z) * n + z * hold;
                __stcg((u64*)&g_hdup[pw][d][jg][2 * b], pack2(hnew, hnew));
                if (WRITE_Y)
                    g_y0[((size_t)t * 1024 + d * HH + jg) * 128 + b] = hnew;
            }
        }

        if (t < SQ - 1) {
            __threadfence();
            __syncthreads();
            if (tid == 0) {
                atomicAdd(&g_bar, 1u);
                const unsigned target = (unsigned)(t + 1) * gridDim.x;
                while (*(volatile unsigned*)&g_bar < target) { __nanosleep(32); }
            }
            __syncthreads();
            __threadfence();
        }
    }
}

__global__ void final_kernel(const float* __restrict__ Ws, const float* __restrict__ bs,
                             float* __restrict__ out)
{
    const int b = threadIdx.x;
    float l0 = bs[0], l1 = bs[1];
#pragma unroll 2
    for (int d = 0; d < 2; d++) {
        for (int j = 0; j < HH; j++) {
            float h = g_hdup[0][d][j][2 * b];   // 400 steps -> final state in buf 0
            int c = d * HH + j;
            l0 = fmaf(h, Ws[c], l0);
            l1 = fmaf(h, Ws[1024 + c], l1);
        }
    }
    float m = fmaxf(l0, l1);
    float lse = m + logf(expf(l0 - m) + expf(l1 - m));
    out[b * 2 + 0] = l0 - lse;
    out[b * 2 + 1] = l1 - lse;
}

extern "C" void kernel_launch(void* const* d_in, const int* in_sizes, int n_in,
                              void* d_out, int out_size)
{
    const int*   X    = (const int*)  d_in[0];
    const float* emb  = (const float*)d_in[1];
    const float* Wih0 = (const float*)d_in[2];
    const float* Whh0 = (const float*)d_in[3];
    const float* bih0 = (const float*)d_in[4];
    const float* bhh0 = (const float*)d_in[5];
    const float* Wih1 = (const float*)d_in[6];
    const float* Whh1 = (const float*)d_in[7];
    const float* bih1 = (const float*)d_in[8];
    const float* bhh1 = (const float*)d_in[9];
    const float* Ws   = (const float*)d_in[10];
    const float* bs   = (const float*)d_in[11];
    float* out = (float*)d_out;

    dim3 ggrid(NCOL / 128, SQ);

    init_kernel<<<64, 256>>>();
    gemm_kernel<true><<<ggrid, 256>>>(emb, X, Wih0, bih0, EE);
    recur_kernel<true><<<128, 256, 49152>>>(Whh0, bhh0);

    init_kernel<<<64, 256>>>();
    gemm_kernel<false><<<ggrid, 256>>>(nullptr, nullptr, Wih1, bih1, 1024);
    recur_kernel<false><<<128, 256, 49152>>>(Whh1, bhh1);

    final_kernel<<<1, 128>>>(Ws, bs, out);
}